// round 2
// baseline (speedup 1.0000x reference)
#include <cuda_runtime.h>

// ---------------------------------------------------------------------------
// DecoderBlock: conv3x3(64->3) + bias + tanh  -> ll [16,3,128,128]
// then two fused inverse Haar levels          -> out [16,3,512,512]
// ---------------------------------------------------------------------------

#define NB   16
#define CIN  64
#define HH   128
#define WW   128

__device__ float g_ll[NB * 3 * HH * WW];   // 3 MB intermediate

// ---------------------------------------------------------------------------
// Kernel A: conv 3x3 pad1, 64->3 + bias + tanh
// Tile 64(w) x 16(h), 128 threads (8,16); thread = 1 row x 8 cols x 3 outch.
// Input channels in chunks of 8 through shared memory, vectorized LDS.
// ---------------------------------------------------------------------------
#define CCHUNK 8
#define TB_W   64
#define TB_H   16
#define SH_Y   (TB_H + 2)        // 18
#define SH_X   72                // 66 used (64 + 2 halo), padded for banking
#define SH_PLANE (SH_Y * SH_X)   // 1296
#define SH_USED  (SH_Y * 66)     // 1188 elements actually loaded per plane

__global__ __launch_bounds__(128) void conv_tanh_kernel(
    const float* __restrict__ fused,
    const float* __restrict__ conv_w,
    const float* __restrict__ conv_b)
{
    __shared__ float s_in[CCHUNK * SH_PLANE];   // 41472 B
    __shared__ float s_w[CIN * 27];             //  6912 B  [cin][o][9]

    const int tx  = threadIdx.x;                // 0..7
    const int ty  = threadIdx.y;                // 0..15
    const int tid = ty * 8 + tx;
    const int b      = blockIdx.z;
    const int base_x = blockIdx.x * TB_W;
    const int base_y = blockIdx.y * TB_H;

    // stage weights: s_w[c*27 + o*9 + t]
    for (int i = tid; i < CIN * 27; i += 128) {
        int c = i / 27, rem = i % 27;
        int o = rem / 9, t = rem % 9;
        s_w[i] = conv_w[o * (CIN * 9) + c * 9 + t];
    }

    float acc[3][8];
#pragma unroll
    for (int o = 0; o < 3; o++)
#pragma unroll
        for (int q = 0; q < 8; q++) acc[o][q] = 0.0f;

    for (int cc0 = 0; cc0 < CIN; cc0 += CCHUNK) {
        __syncthreads();
        // load CCHUNK planes with halo (cols 0..65 <-> gw base_x-1..base_x+64)
        for (int c = 0; c < CCHUNK; c++) {
            const float* gp = &fused[((b * CIN + cc0 + c) * HH) * WW];
            float* sp = &s_in[c * SH_PLANE];
            for (int i = tid; i < SH_USED; i += 128) {
                int r   = i / 66;
                int col = i - r * 66;
                int gh  = base_y + r - 1;
                int gw  = base_x + col - 1;
                float v = 0.0f;
                if (gh >= 0 && gh < HH && gw >= 0 && gw < WW)
                    v = __ldg(&gp[gh * WW + gw]);
                sp[r * SH_X + col] = v;
            }
        }
        __syncthreads();

#pragma unroll
        for (int c = 0; c < CCHUNK; c++) {
            // weights for this input channel (broadcast LDS)
            const float* wp = &s_w[(cc0 + c) * 27];
            float wv[27];
#pragma unroll
            for (int t = 0; t < 27; t++) wv[t] = wp[t];

            const float* sp = &s_in[c * SH_PLANE];
#pragma unroll
            for (int ky = 0; ky < 3; ky++) {
                // 10 consecutive inputs: smem cols tx*8 .. tx*8+9 (16B aligned)
                const float* rp = sp + (ty + ky) * SH_X + tx * 8;
                float4 va = *reinterpret_cast<const float4*>(rp);
                float4 vb = *reinterpret_cast<const float4*>(rp + 4);
                float2 vc = *reinterpret_cast<const float2*>(rp + 8);
                float x[10];
                x[0]=va.x; x[1]=va.y; x[2]=va.z; x[3]=va.w;
                x[4]=vb.x; x[5]=vb.y; x[6]=vb.z; x[7]=vb.w;
                x[8]=vc.x; x[9]=vc.y;
#pragma unroll
                for (int o = 0; o < 3; o++)
#pragma unroll
                    for (int kx = 0; kx < 3; kx++) {
                        const float w = wv[o * 9 + ky * 3 + kx];
#pragma unroll
                        for (int q = 0; q < 8; q++)
                            acc[o][q] += w * x[q + kx];
                    }
            }
        }
    }

    // bias + tanh + store (two float4 per out channel)
    const int gy = base_y + ty;
    const int gx = base_x + tx * 8;
#pragma unroll
    for (int o = 0; o < 3; o++) {
        const float bias = conv_b[o];
        float4 v0, v1;
        v0.x = tanhf(acc[o][0] + bias); v0.y = tanhf(acc[o][1] + bias);
        v0.z = tanhf(acc[o][2] + bias); v0.w = tanhf(acc[o][3] + bias);
        v1.x = tanhf(acc[o][4] + bias); v1.y = tanhf(acc[o][5] + bias);
        v1.z = tanhf(acc[o][6] + bias); v1.w = tanhf(acc[o][7] + bias);
        float* op = &g_ll[((b * 3 + o) * HH + gy) * WW + gx];
        *reinterpret_cast<float4*>(op)     = v0;
        *reinterpret_cast<float4*>(op + 4) = v1;
    }
}

// ---------------------------------------------------------------------------
// Kernel B: fused double inverse Haar.
// Thread handles 2 consecutive coarse pixels (w0 = 2*tx, 2*tx+1):
//   float2 ll + 3x float2 hf2 loads, 3x2 float4 hf1 loads,
//   writes 4 rows x 2 float4 of the 8-wide output strip.
// Butterfly (a=LL, lh, hl, hh scaled 2x-1):
//   o00=.5(a-lh-hl+hh) o01=.5(a-lh+hl-hh) o10=.5(a+lh-hl-hh) o11=.5(a+lh+hl+hh)
// ---------------------------------------------------------------------------
__global__ __launch_bounds__(256) void iwt2_kernel(
    const float* __restrict__ hf1,
    const float* __restrict__ hf2,
    float* __restrict__ out)
{
    const int tx = threadIdx.x;                  // 0..63  -> w0 = 2*tx(+1)
    const int h0 = blockIdx.x * 4 + threadIdx.y; // 0..127
    const int z  = blockIdx.y;                   // b*3 + c
    const int b  = z / 3;
    const int c  = z - b * 3;

    const float2 ll2 = *reinterpret_cast<const float2*>(
        &g_ll[(z * HH + h0) * WW + 2 * tx]);

    const int hf2base = ((b * 9 + 3 * c) * HH + h0) * WW + 2 * tx;
    const float2 lh2 = __ldg(reinterpret_cast<const float2*>(&hf2[hf2base]));
    const float2 hl2 = __ldg(reinterpret_cast<const float2*>(&hf2[hf2base + HH*WW]));
    const float2 hh2 = __ldg(reinterpret_cast<const float2*>(&hf2[hf2base + 2*HH*WW]));

    // hf1: 3 channels x 2 rows, 4 consecutive cols (float4), 256x256 planes
    const int h1 = 2 * h0;
    float4 v1[3][2];
#pragma unroll
    for (int k = 0; k < 3; k++)
#pragma unroll
        for (int p0 = 0; p0 < 2; p0++)
            v1[k][p0] = __ldg(reinterpret_cast<const float4*>(
                &hf1[((b * 9 + 3 * c + k) * 256 + (h1 + p0)) * 256 + 4 * tx]));

    float o16[4][8];
#pragma unroll
    for (int s = 0; s < 2; s++) {
        const float a  = s ? ll2.y : ll2.x;
        const float lh = 2.0f * (s ? lh2.y : lh2.x) - 1.0f;
        const float hl = 2.0f * (s ? hl2.y : hl2.x) - 1.0f;
        const float hh = 2.0f * (s ? hh2.y : hh2.x) - 1.0f;

        float cur[2][2];
        cur[0][0] = 0.5f * (a - lh - hl + hh);
        cur[0][1] = 0.5f * (a - lh + hl - hh);
        cur[1][0] = 0.5f * (a + lh - hl - hh);
        cur[1][1] = 0.5f * (a + lh + hl + hh);

#pragma unroll
        for (int p0 = 0; p0 < 2; p0++)
#pragma unroll
            for (int q0 = 0; q0 < 2; q0++) {
                const float a2 = cur[p0][q0];
                const int ci = 2 * s + q0;   // component in float4 (col 4*tx+ci)
                const float* f0 = reinterpret_cast<const float*>(&v1[0][p0]);
                const float* f1 = reinterpret_cast<const float*>(&v1[1][p0]);
                const float* f2 = reinterpret_cast<const float*>(&v1[2][p0]);
                const float lh1 = 2.0f * f0[ci] - 1.0f;
                const float hl1 = 2.0f * f1[ci] - 1.0f;
                const float hh1 = 2.0f * f2[ci] - 1.0f;
                const int colb = 4 * s + 2 * q0;
                o16[2*p0 + 0][colb + 0] = 0.5f * (a2 - lh1 - hl1 + hh1);
                o16[2*p0 + 0][colb + 1] = 0.5f * (a2 - lh1 + hl1 - hh1);
                o16[2*p0 + 1][colb + 0] = 0.5f * (a2 + lh1 - hl1 - hh1);
                o16[2*p0 + 1][colb + 1] = 0.5f * (a2 + lh1 + hl1 + hh1);
            }
    }

    // 4 output rows x 8 cols -> 2 float4 stores per row, fully coalesced
#pragma unroll
    for (int r = 0; r < 4; r++) {
        float* op = &out[((long)z * 512 + (4 * h0 + r)) * 512 + 8 * tx];
        float4 w0, w1;
        w0.x = o16[r][0]; w0.y = o16[r][1]; w0.z = o16[r][2]; w0.w = o16[r][3];
        w1.x = o16[r][4]; w1.y = o16[r][5]; w1.z = o16[r][6]; w1.w = o16[r][7];
        *reinterpret_cast<float4*>(op)     = w0;
        *reinterpret_cast<float4*>(op + 4) = w1;
    }
}

// ---------------------------------------------------------------------------
extern "C" void kernel_launch(void* const* d_in, const int* in_sizes, int n_in,
                              void* d_out, int out_size)
{
    const float* fused  = (const float*)d_in[0];
    const float* hf1    = (const float*)d_in[1];
    const float* hf2    = (const float*)d_in[2];
    const float* conv_w = (const float*)d_in[3];
    const float* conv_b = (const float*)d_in[4];
    float* out = (float*)d_out;

    dim3 cb(8, 16);
    dim3 cg(WW / TB_W, HH / TB_H, NB);      // (2,8,16) = 256 CTAs
    conv_tanh_kernel<<<cg, cb>>>(fused, conv_w, conv_b);

    dim3 ib(64, 4);
    dim3 ig(HH / 4, NB * 3);                // (32,48) = 1536 CTAs
    iwt2_kernel<<<ig, ib>>>(hf1, hf2, out);
}

// round 3
// speedup vs baseline: 4.8114x; 4.8114x over previous
#include <cuda_runtime.h>

// ---------------------------------------------------------------------------
// DecoderBlock: conv3x3(64->3) + bias + tanh  -> ll [16,3,128,128]
// then two fused inverse Haar levels          -> out [16,3,512,512]
// ---------------------------------------------------------------------------

#define NB   16
#define CIN  64
#define HH   128
#define WW   128
#define HW   (HH * WW)          // 16384

__device__ float g_ll[NB * 3 * HH * WW];   // 3 MB intermediate

// ---------------------------------------------------------------------------
// Kernel A: streaming conv 3x3 pad1, 64->3 + bias + tanh.
// No input staging: reads flow through L1 (9x spatial reuse via cache).
// Thread = 1 row x 4 cols x 3 outch. CTA = 128 threads (32,4) covering a
// full 128-wide row band of 4 rows. Grid = 32 row-bands x 16 batches = 512.
// Channel loop double-buffered in registers; weights staged to smem once.
// ---------------------------------------------------------------------------
__global__ __launch_bounds__(128) void conv_tanh_kernel(
    const float* __restrict__ fused,
    const float* __restrict__ conv_w,
    const float* __restrict__ conv_b)
{
    __shared__ float s_w[CIN * 32];   // 8 KB, [c][o*9+t] padded to 32

    const int tx  = threadIdx.x;              // 0..31 -> cols 4tx..4tx+3
    const int ty  = threadIdx.y;              // 0..3
    const int tid = ty * 32 + tx;
    const int b   = blockIdx.y;
    const int gy  = blockIdx.x * 4 + ty;      // output row 0..127

    // stage weights once: s_w[c*32 + o*9 + t] (src layout [o][c][3][3])
    for (int i = tid; i < CIN * 27; i += 128) {
        int c = i / 27, r = i % 27;
        s_w[c * 32 + r] = conv_w[(r / 9) * (CIN * 9) + c * 9 + (r % 9)];
    }
    __syncthreads();

    const bool vtop = (gy > 0);
    const bool vbot = (gy < HH - 1);
    const bool vl   = (tx > 0);
    const bool vr   = (tx < 31);
    // base pointer at (channel 0, row gy-1, col 4tx); predicated if OOB
    const float* p0 = fused + (long)b * CIN * HW + (gy - 1) * WW + 4 * tx;

    float x0[3][6], x1[3][6];

    // load the 3x6 input patch for channel c into x[][]
    auto loadch = [&](int c, float (&x)[3][6]) {
        const bool rv[3] = { vtop, true, vbot };
#pragma unroll
        for (int k = 0; k < 3; k++) {
            const float* rp = p0 + c * HW + k * WW;
            float4 m = make_float4(0.f, 0.f, 0.f, 0.f);
            float l = 0.f, r = 0.f;
            if (rv[k]) {
                m = __ldg(reinterpret_cast<const float4*>(rp));
                if (vl) l = __ldg(rp - 1);
                if (vr) r = __ldg(rp + 4);
            }
            x[k][0] = l;   x[k][1] = m.x; x[k][2] = m.y;
            x[k][3] = m.z; x[k][4] = m.w; x[k][5] = r;
        }
    };

    float acc[3][4];
#pragma unroll
    for (int o = 0; o < 3; o++)
#pragma unroll
        for (int q = 0; q < 4; q++) acc[o][q] = 0.0f;

    auto compute = [&](int c, float (&x)[3][6]) {
        float4 w4[8];
#pragma unroll
        for (int k = 0; k < 8; k++)
            w4[k] = *reinterpret_cast<const float4*>(&s_w[c * 32 + 4 * k]);
        const float* w = reinterpret_cast<const float*>(w4);
#pragma unroll
        for (int o = 0; o < 3; o++)
#pragma unroll
            for (int ky = 0; ky < 3; ky++)
#pragma unroll
                for (int kx = 0; kx < 3; kx++) {
                    const float wv = w[o * 9 + ky * 3 + kx];
#pragma unroll
                    for (int q = 0; q < 4; q++)
                        acc[o][q] += wv * x[ky][q + kx];
                }
    };

    loadch(0, x0);
#pragma unroll 1
    for (int c = 0; c < CIN; c += 2) {
        loadch(c + 1, x1);
        compute(c, x0);
        if (c + 2 < CIN) loadch(c + 2, x0);
        compute(c + 1, x1);
    }

    // bias + tanh + one float4 store per out channel
#pragma unroll
    for (int o = 0; o < 3; o++) {
        const float bias = conv_b[o];
        float4 v;
        v.x = tanhf(acc[o][0] + bias);
        v.y = tanhf(acc[o][1] + bias);
        v.z = tanhf(acc[o][2] + bias);
        v.w = tanhf(acc[o][3] + bias);
        *reinterpret_cast<float4*>(
            &g_ll[((b * 3 + o) * HH + gy) * WW + 4 * tx]) = v;
    }
}

// ---------------------------------------------------------------------------
// Kernel B: fused double inverse Haar (R1 version — 15.1us, occ 77%).
// One thread per coarse ll pixel: level-1 butterfly with hf2 -> 2x2,
// level-2 with hf1 -> 4x4 output block, written as 4 float4 rows.
// ---------------------------------------------------------------------------
__global__ __launch_bounds__(256) void iwt2_kernel(
    const float* __restrict__ hf1,
    const float* __restrict__ hf2,
    float* __restrict__ out)
{
    const int w0 = threadIdx.x;                        // 0..127
    const int h0 = blockIdx.x * 2 + threadIdx.y;       // 0..127
    const int z  = blockIdx.y;                         // b*3 + c
    const int b  = z / 3;
    const int c  = z - b * 3;

    const float a = g_ll[(z * HH + h0) * WW + w0];

    const int hf2base = ((b * 9 + 3 * c) * HH + h0) * WW + w0;
    const float lh = 2.0f * __ldg(&hf2[hf2base            ]) - 1.0f;
    const float hl = 2.0f * __ldg(&hf2[hf2base + HH * WW  ]) - 1.0f;
    const float hh = 2.0f * __ldg(&hf2[hf2base + 2*HH*WW  ]) - 1.0f;

    float cur[2][2];
    cur[0][0] = 0.5f * (a - lh - hl + hh);
    cur[0][1] = 0.5f * (a - lh + hl - hh);
    cur[1][0] = 0.5f * (a + lh - hl - hh);
    cur[1][1] = 0.5f * (a + lh + hl + hh);

    const int h1 = 2 * h0;
    const int w1 = 2 * w0;
    float2 v[3][2];
#pragma unroll
    for (int k = 0; k < 3; k++) {
#pragma unroll
        for (int p0 = 0; p0 < 2; p0++) {
            const float2* ptr = reinterpret_cast<const float2*>(
                &hf1[((b * 9 + 3 * c + k) * 256 + (h1 + p0)) * 256 + w1]);
            v[k][p0] = __ldg(ptr);
        }
    }

    float o16[4][4];
#pragma unroll
    for (int p0 = 0; p0 < 2; p0++) {
#pragma unroll
        for (int q0 = 0; q0 < 2; q0++) {
            const float a2  = cur[p0][q0];
            const float lh1 = 2.0f * (q0 == 0 ? v[0][p0].x : v[0][p0].y) - 1.0f;
            const float hl1 = 2.0f * (q0 == 0 ? v[1][p0].x : v[1][p0].y) - 1.0f;
            const float hh1 = 2.0f * (q0 == 0 ? v[2][p0].x : v[2][p0].y) - 1.0f;
            o16[2 * p0 + 0][2 * q0 + 0] = 0.5f * (a2 - lh1 - hl1 + hh1);
            o16[2 * p0 + 0][2 * q0 + 1] = 0.5f * (a2 - lh1 + hl1 - hh1);
            o16[2 * p0 + 1][2 * q0 + 0] = 0.5f * (a2 + lh1 - hl1 - hh1);
            o16[2 * p0 + 1][2 * q0 + 1] = 0.5f * (a2 + lh1 + hl1 + hh1);
        }
    }

#pragma unroll
    for (int r = 0; r < 4; r++) {
        float4 row;
        row.x = o16[r][0]; row.y = o16[r][1];
        row.z = o16[r][2]; row.w = o16[r][3];
        *reinterpret_cast<float4*>(
            &out[((long)z * 512 + (4 * h0 + r)) * 512 + 4 * w0]) = row;
    }
}

// ---------------------------------------------------------------------------
extern "C" void kernel_launch(void* const* d_in, const int* in_sizes, int n_in,
                              void* d_out, int out_size)
{
    const float* fused  = (const float*)d_in[0];
    const float* hf1    = (const float*)d_in[1];
    const float* hf2    = (const float*)d_in[2];
    const float* conv_w = (const float*)d_in[3];
    const float* conv_b = (const float*)d_in[4];
    float* out = (float*)d_out;

    dim3 cb(32, 4);
    dim3 cg(HH / 4, NB);                    // (32,16) = 512 CTAs
    conv_tanh_kernel<<<cg, cb>>>(fused, conv_w, conv_b);

    dim3 ib(128, 2);
    dim3 ig(HH / 2, NB * 3);                // (64,48) = 3072 CTAs
    iwt2_kernel<<<ig, ib>>>(hf1, hf2, out);
}